// round 17
// baseline (speedup 1.0000x reference)
#include <cuda_runtime.h>
#include <math.h>

#define GDIM 4
#define SDIM 2048
#define TTOT 8192
#define MDIM 1024
#define EDIM 64
#define NBLK 128          // gemm blocks: 64 tokens each

typedef unsigned long long ull;

__device__ int   g_idx[TTOT];
__device__ float g_gate[TTOT];
__device__ int   g_pos[TTOT];
__device__ int   g_counts[GDIM * EDIM];
__device__ float g_proxy[NBLK * EDIM];

// ---------------------------------------------------------------------------
// K1: logits = x @ W, softmax, argmax, proxy sums.
// 512 threads / 16 warps: warp w -> experts [4w,4w+4) (2 f32x2 pairs),
// lane l -> tokens {l, l+32}. 4 warps/SMSP hides LDS/FFMA latency.
// x staged PRE-DUPLICATED ({x,x} per m) -> inner loop has zero movs:
//   per mp: 2 LDS.128 (x, contiguous conflict-free) + 2 LDS.128 (W, uniform)
//           + 8 FFMA2.
// Double-buffered chunks of 32 m. Per-(token,expert) accumulation strictly
// ascending in m -> logits bit-identical to R6/R15.
// ---------------------------------------------------------------------------
__global__ __launch_bounds__(512, 1)
void k_gemm(const float* __restrict__ x, const float* __restrict__ Wt) {
    __shared__ __align__(16) ulonglong2 xs[2][16][64];  // [buf][mp][tok] {dup m0, dup m1}  32KB
    __shared__ __align__(16) ulonglong2 wv[2][16][32];  // [buf][mp][pair] {(e0m0,e1m0),(e0m1,e1m1)} 16KB
    // overlays (after mainloop): lg = (float*)xs (64x65), isum = (float*)wv

    const int tid = threadIdx.x;
    const int w = tid >> 5;          // 0..15
    const int l = tid & 31;
    const int tb = blockIdx.x * 64;

    ull acc[2][2] = {};              // [token a/b][pair]

    // staging assignment
    const int xt = tid & 63;         // token
    const int xm = tid >> 6;         // mp for entry0 (entry1: xm+8)
    const int wm = tid >> 5;         // W entry mp (0..15)
    const int wpp = tid & 31;        // W pair

    float2 xr0, xr1;
    ull wr0, wr1;

    // ---- stage chunk 0 ----
    {
        const float* xrow = x + (size_t)(tb + xt) * MDIM;
        xr0 = *(const float2*)(xrow + 2 * xm);
        xr1 = *(const float2*)(xrow + 2 * (xm + 8));
        wr0 = *(const ull*)(Wt + (size_t)(2 * wm) * EDIM + 2 * wpp);
        wr1 = *(const ull*)(Wt + (size_t)(2 * wm + 1) * EDIM + 2 * wpp);
        ull a0, a1, b0, b1;
        asm("mov.b64 %0, {%1, %1};" : "=l"(a0) : "f"(xr0.x));
        asm("mov.b64 %0, {%1, %1};" : "=l"(a1) : "f"(xr0.y));
        asm("mov.b64 %0, {%1, %1};" : "=l"(b0) : "f"(xr1.x));
        asm("mov.b64 %0, {%1, %1};" : "=l"(b1) : "f"(xr1.y));
        xs[0][xm][xt]     = make_ulonglong2(a0, a1);
        xs[0][xm + 8][xt] = make_ulonglong2(b0, b1);
        wv[0][wm][wpp]    = make_ulonglong2(wr0, wr1);
    }
    __syncthreads();

    for (int ch = 0; ch < 32; ++ch) {
        const int cb = ch & 1, nb = cb ^ 1;

        if (ch < 31) {   // prefetch next chunk into regs (overlaps compute)
            const int mb = (ch + 1) * 32;
            const float* xrow = x + (size_t)(tb + xt) * MDIM + mb;
            xr0 = *(const float2*)(xrow + 2 * xm);
            xr1 = *(const float2*)(xrow + 2 * (xm + 8));
            wr0 = *(const ull*)(Wt + (size_t)(mb + 2 * wm) * EDIM + 2 * wpp);
            wr1 = *(const ull*)(Wt + (size_t)(mb + 2 * wm + 1) * EDIM + 2 * wpp);
        }

        const ulonglong2* xc = &xs[cb][0][0];
        const ulonglong2* wc = &wv[cb][0][0];
#pragma unroll
        for (int mp = 0; mp < 16; ++mp) {
            ulonglong2 xa = xc[mp * 64 + l];          // token l   : {dup m0, dup m1}
            ulonglong2 xb = xc[mp * 64 + l + 32];     // token l+32
            ulonglong2 w0 = wc[mp * 32 + 2 * w];      // pair 0 (uniform)
            ulonglong2 w1 = wc[mp * 32 + 2 * w + 1];  // pair 1 (uniform)
            asm("fma.rn.f32x2 %0, %1, %2, %0;" : "+l"(acc[0][0]) : "l"(w0.x), "l"(xa.x));
            asm("fma.rn.f32x2 %0, %1, %2, %0;" : "+l"(acc[0][0]) : "l"(w0.y), "l"(xa.y));
            asm("fma.rn.f32x2 %0, %1, %2, %0;" : "+l"(acc[0][1]) : "l"(w1.x), "l"(xa.x));
            asm("fma.rn.f32x2 %0, %1, %2, %0;" : "+l"(acc[0][1]) : "l"(w1.y), "l"(xa.y));
            asm("fma.rn.f32x2 %0, %1, %2, %0;" : "+l"(acc[1][0]) : "l"(w0.x), "l"(xb.x));
            asm("fma.rn.f32x2 %0, %1, %2, %0;" : "+l"(acc[1][0]) : "l"(w0.y), "l"(xb.y));
            asm("fma.rn.f32x2 %0, %1, %2, %0;" : "+l"(acc[1][1]) : "l"(w1.x), "l"(xb.x));
            asm("fma.rn.f32x2 %0, %1, %2, %0;" : "+l"(acc[1][1]) : "l"(w1.y), "l"(xb.y));
        }

        if (ch < 31) {   // store prefetched regs into the other buffer
            ull a0, a1, b0, b1;
            asm("mov.b64 %0, {%1, %1};" : "=l"(a0) : "f"(xr0.x));
            asm("mov.b64 %0, {%1, %1};" : "=l"(a1) : "f"(xr0.y));
            asm("mov.b64 %0, {%1, %1};" : "=l"(b0) : "f"(xr1.x));
            asm("mov.b64 %0, {%1, %1};" : "=l"(b1) : "f"(xr1.y));
            xs[nb][xm][xt]     = make_ulonglong2(a0, a1);
            xs[nb][xm + 8][xt] = make_ulonglong2(b0, b1);
            wv[nb][wm][wpp]    = make_ulonglong2(wr0, wr1);
        }
        __syncthreads();
    }

    // logits -> smem overlay (pitch 65); buffers are dead past final sync
    float* lg   = (float*)&xs[0][0][0];
    float* isum = (float*)&wv[0][0][0];
#pragma unroll
    for (int tt = 0; tt < 2; ++tt) {
        int t = l + 32 * tt;
#pragma unroll
        for (int j = 0; j < 2; ++j) {
            float lo, hi;
            asm("mov.b64 {%0, %1}, %2;" : "=f"(lo), "=f"(hi) : "l"(acc[tt][j]));
            lg[t * 65 + 4 * w + 2 * j]     = lo;
            lg[t * 65 + 4 * w + 2 * j + 1] = hi;
        }
    }
    __syncthreads();

    if (tid < 64) {
        const int t = tid;
        float mx = -1e30f; int am = 0;
        for (int e = 0; e < EDIM; ++e) {
            float v = lg[t * 65 + e];
            if (v > mx) { mx = v; am = e; }     // first-max semantics
        }
        float sm = 0.0f;
        for (int e = 0; e < EDIM; ++e) {
            float p = expf(lg[t * 65 + e] - mx);
            lg[t * 65 + e] = p;
            sm += p;
        }
        float inv = 1.0f / sm;
        isum[t] = inv;
        g_idx[tb + t]  = am;
        g_gate[tb + t] = inv;
    }
    __syncthreads();

    if (tid < 64) {
        const int e = tid;
        float s = 0.0f;
        for (int t = 0; t < 64; ++t) s += lg[t * 65 + e] * isum[t];
        g_proxy[blockIdx.x * 64 + e] = s;
    }
}

// ---------------------------------------------------------------------------
// K2: exclusive running position within each (group, expert). (R6 exact)
// ---------------------------------------------------------------------------
__global__ __launch_bounds__(1024, 1)
void k_pos() {
    __shared__ int idx_s[2048];
    __shared__ int cnt_s[16 * 64];
    __shared__ int pos_s[2048];

    const int g = blockIdx.x;
    const int tid = threadIdx.x;

    idx_s[tid]        = g_idx[g * 2048 + tid];
    idx_s[tid + 1024] = g_idx[g * 2048 + tid + 1024];
    __syncthreads();

    const int c = tid >> 6;
    const int e = tid & 63;

    int cnt = 0;
#pragma unroll 8
    for (int i = 0; i < 128; ++i) cnt += (idx_s[c * 128 + i] == e);
    cnt_s[c * 64 + e] = cnt;
    __syncthreads();

    int pre = 0;
    for (int cc = 0; cc < c; ++cc) pre += cnt_s[cc * 64 + e];
    if (c == 15) g_counts[g * 64 + e] = pre + cnt;

    int run = pre;
#pragma unroll 4
    for (int i = 0; i < 128; ++i) {
        int s = c * 128 + i;
        if (idx_s[s] == e) pos_s[s] = run++;
    }
    __syncthreads();

    g_pos[g * 2048 + tid]        = pos_s[tid];
    g_pos[g * 2048 + tid + 1024] = pos_s[tid + 1024];
}

// ---------------------------------------------------------------------------
// K3: fused fill + scatter + aux (R6 exact — proven ~92us at ~7.3TB/s).
// ---------------------------------------------------------------------------
__global__ __launch_bounds__(256, 8)
void k_fill(float* __restrict__ out, int C, size_t N) {
    const int r = blockIdx.x;
    const int tid = threadIdx.x;

    if (r < 2 * TTOT) {
        const int sec = (r >= TTOT);
        const int t = sec ? r - TTOT : r;

        const int p = g_pos[t];
        const int tgt = (p < C) ? (g_idx[t] * C + p) : -1;
        const float val = sec ? 1.0f : g_gate[t];
        const int tf4 = tgt >> 2;

        float4* row = (float4*)(out + (size_t)sec * N + (size_t)t * (size_t)(EDIM * C));
        const int nf4 = (EDIM * C) >> 2;                 // 2560 for C=160

        for (int f = tid; f < nf4; f += 256) {
            float4 v = make_float4(0.f, 0.f, 0.f, 0.f);
            if (f == tf4) ((float*)&v)[tgt & 3] = val;
            __stcs(row + f, v);
        }
    } else {
        __shared__ float red[256];
        const int g = tid >> 6;
        const int e = tid & 63;
        float px = 0.0f;
        for (int b = 0; b < 32; ++b) px += g_proxy[(g * 32 + b) * 64 + e];
        const float denom = 1.0f + 1e-6f;
        float d1 = ((float)g_counts[g * 64 + e] / (float)SDIM) / denom;
        float dp = (px / (float)SDIM) / denom;
        red[tid] = d1 * dp;
        __syncthreads();
        for (int s = 128; s > 0; s >>= 1) {
            if (tid < s) red[tid] += red[tid + s];
            __syncthreads();
        }
        if (tid == 0)
            out[2 * N] = (red[0] / 256.0f) * ((float)EDIM * (float)EDIM * 0.01f);
    }
}

// ---------------------------------------------------------------------------
extern "C" void kernel_launch(void* const* d_in, const int* in_sizes, int n_in,
                              void* d_out, int out_size) {
    const float* x  = (const float*)d_in[0];
    const float* Wt = (const float*)d_in[1];
    float* out = (float*)d_out;

    size_t N = ((size_t)out_size - 1) / 2;
    int C = (int)(N / ((size_t)TTOT * EDIM));   // 160

    k_gemm<<<NBLK, 512>>>(x, Wt);
    k_pos<<<GDIM, 1024>>>();
    k_fill<<<2 * TTOT + 1, 256>>>(out, C, N);
}